// round 1
// baseline (speedup 1.0000x reference)
#include <cuda_runtime.h>
#include <cuda_bf16.h>

#define BB 32
#define SS 2048
#define EMB 256
#define NPOS (BB*SS)
#define NSK 1000
#define TT 64
#define NT (SS/TT)
#define KC 64
#define SPAD 66   // smem row stride in bf16 (132B = 33 banks -> conflict-free frags)

// Scratch: gathered embeddings as bf16 (tile rows are contiguous sequence positions)
__device__ __nv_bfloat16 g_srcA[NPOS*EMB];  // alpha_inter_W[inters]
__device__ __nv_bfloat16 g_srcB[NPOS*EMB];  // beta_inter_W[inters]
__device__ __nv_bfloat16 g_tgtA[NPOS*EMB];  // alpha_skill_W[skills]
__device__ __nv_bfloat16 g_tgtB[NPOS*EMB];  // beta_skill_W[skills]
__device__ float g_ts[NPOS];
__device__ float g_bias[NPOS];

__device__ __forceinline__ float bflo(unsigned u){ return __int_as_float(u << 16); }
__device__ __forceinline__ float bfhi(unsigned u){ return __int_as_float(u & 0xffff0000u); }

// 2^z via floor-split + degree-6 Taylor on [0,1): rel err ~1e-5, all FMA-pipe.
__device__ __forceinline__ float fast_exp2(float z){
    z = fminf(fmaxf(z, -126.f), 126.f);
    float fl = floorf(z);
    float f  = z - fl;
    float w = fmaf(f, 1.5403530393e-4f, 1.3333558146e-3f);
    w = fmaf(f, w, 9.6181291076e-3f);
    w = fmaf(f, w, 5.5504108665e-2f);
    w = fmaf(f, w, 2.4022650696e-1f);
    w = fmaf(f, w, 6.9314718056e-1f);
    w = fmaf(f, w, 1.0f);
    int n = (int)fl;
    return w * __int_as_float((n + 127) << 23);
}

__global__ void gather_kernel(const int* __restrict__ skills, const int* __restrict__ problems,
                              const int* __restrict__ times,  const int* __restrict__ labels,
                              const float* __restrict__ aI, const float* __restrict__ aS,
                              const float* __restrict__ bI, const float* __restrict__ bS,
                              const float* __restrict__ pb, const float* __restrict__ sb)
{
    int idx = blockIdx.x * blockDim.x + threadIdx.x;
    if (idx >= NPOS * (EMB/4)) return;
    int pos = idx >> 6;
    int e   = (idx & 63) << 2;
    int sk  = skills[pos];
    int inter = sk + labels[pos] * NSK;
    float4 vA = *(const float4*)(aI + (size_t)inter*EMB + e);
    float4 vB = *(const float4*)(bI + (size_t)inter*EMB + e);
    float4 tA = *(const float4*)(aS + (size_t)sk*EMB + e);
    float4 tB = *(const float4*)(bS + (size_t)sk*EMB + e);
    size_t o = (size_t)pos*EMB + e;
    *(__nv_bfloat162*)(g_srcA + o)     = __floats2bfloat162_rn(vA.x, vA.y);
    *(__nv_bfloat162*)(g_srcA + o + 2) = __floats2bfloat162_rn(vA.z, vA.w);
    *(__nv_bfloat162*)(g_srcB + o)     = __floats2bfloat162_rn(vB.x, vB.y);
    *(__nv_bfloat162*)(g_srcB + o + 2) = __floats2bfloat162_rn(vB.z, vB.w);
    *(__nv_bfloat162*)(g_tgtA + o)     = __floats2bfloat162_rn(tA.x, tA.y);
    *(__nv_bfloat162*)(g_tgtA + o + 2) = __floats2bfloat162_rn(tA.z, tA.w);
    *(__nv_bfloat162*)(g_tgtB + o)     = __floats2bfloat162_rn(tB.x, tB.y);
    *(__nv_bfloat162*)(g_tgtB + o + 2) = __floats2bfloat162_rn(tB.z, tB.w);
    if ((idx & 63) == 0) {
        g_ts[pos]   = (float)times[pos] / 1000.0f;   // true divide: bit-match reference
        g_bias[pos] = pb[problems[pos]] + sb[sk];
    }
}

__global__ void __launch_bounds__(256, 2) hawkes_main(float* __restrict__ out)
{
    __shared__ __nv_bfloat16 sSA[TT][SPAD];
    __shared__ __nv_bfloat16 sSB[TT][SPAD];
    __shared__ __nv_bfloat16 sTA[TT][SPAD];
    __shared__ __nv_bfloat16 sTB[TT][SPAD];
    __shared__ float sTsS[TT];
    __shared__ float sTsT[TT];
    __shared__ float sRed[16][TT];

    const int b   = blockIdx.y;
    const int jt  = (int)gridDim.x - 1 - (int)blockIdx.x;   // big tiles first (balance)
    const int tid = threadIdx.x;
    const int tx  = tid & 15;
    const int ty  = tid >> 4;
    const int tgt_base = b * SS + jt * TT;

    if (tid < TT) sTsT[tid] = g_ts[tgt_base + tid];
    __syncthreads();

    float tsT[4];
    #pragma unroll
    for (int q = 0; q < 4; ++q) tsT[q] = sTsT[tx + (q << 4)];

    float colsum[4] = {0.f, 0.f, 0.f, 0.f};

    const int lr = tid & 63;    // loader: row within tile
    const int lw = tid >> 6;    // loader: which of 4 tiles

    for (int it = 0; it <= jt; ++it) {
        const int src_base = b * SS + it * TT;
        float accA[4][4], accB[4][4];
        #pragma unroll
        for (int r = 0; r < 4; ++r)
            #pragma unroll
            for (int q = 0; q < 4; ++q) { accA[r][q] = 0.f; accB[r][q] = 0.f; }

        #pragma unroll 1
        for (int kc = 0; kc < EMB; kc += KC) {
            __syncthreads();   // protect smem reuse (prev frags / prev sTsS readers)
            if (kc == 0 && tid < TT) sTsS[tid] = g_ts[src_base + tid];

            // load one 64x64 bf16 chunk of each of the 4 tiles (1 row per thread)
            const __nv_bfloat16* gsrc;
            __nv_bfloat16* sdst;
            if      (lw == 0) { gsrc = g_srcA + (size_t)(src_base + lr)*EMB + kc; sdst = &sSA[lr][0]; }
            else if (lw == 1) { gsrc = g_srcB + (size_t)(src_base + lr)*EMB + kc; sdst = &sSB[lr][0]; }
            else if (lw == 2) { gsrc = g_tgtA + (size_t)(tgt_base + lr)*EMB + kc; sdst = &sTA[lr][0]; }
            else              { gsrc = g_tgtB + (size_t)(tgt_base + lr)*EMB + kc; sdst = &sTB[lr][0]; }
            {
                const uint4* g4 = (const uint4*)gsrc;
                unsigned* s32 = (unsigned*)sdst;   // 4B-aligned (132B row stride)
                #pragma unroll
                for (int u = 0; u < 8; ++u) {
                    uint4 v = g4[u];
                    s32[u*4 + 0] = v.x; s32[u*4 + 1] = v.y;
                    s32[u*4 + 2] = v.z; s32[u*4 + 3] = v.w;
                }
            }
            __syncthreads();

            #pragma unroll 4
            for (int kk = 0; kk < KC; kk += 2) {
                unsigned a_s[4], b_s[4], a_t[4], b_t[4];
                #pragma unroll
                for (int r = 0; r < 4; ++r) {
                    a_s[r] = *(const unsigned*)&sSA[(ty << 2) + r][kk];
                    b_s[r] = *(const unsigned*)&sSB[(ty << 2) + r][kk];
                }
                #pragma unroll
                for (int q = 0; q < 4; ++q) {
                    a_t[q] = *(const unsigned*)&sTA[tx + (q << 4)][kk];
                    b_t[q] = *(const unsigned*)&sTB[tx + (q << 4)][kk];
                }
                #pragma unroll
                for (int r = 0; r < 4; ++r) {
                    float aslo = bflo(a_s[r]), ashi = bfhi(a_s[r]);
                    float bslo = bflo(b_s[r]), bshi = bfhi(b_s[r]);
                    #pragma unroll
                    for (int q = 0; q < 4; ++q) {
                        accA[r][q] = fmaf(aslo, bflo(a_t[q]), accA[r][q]);
                        accA[r][q] = fmaf(ashi, bfhi(a_t[q]), accA[r][q]);
                        accB[r][q] = fmaf(bslo, bflo(b_t[q]), accB[r][q]);
                        accB[r][q] = fmaf(bshi, bfhi(b_t[q]), accB[r][q]);
                    }
                }
            }
        }

        // epilogue for this (it, jt) tile pair
        const bool offdiag = (it < jt);
        float tsS[4];
        #pragma unroll
        for (int r = 0; r < 4; ++r) tsS[r] = sTsS[(ty << 2) + r];

        const float NEG_INV_LN5 = -0.6213349345596119f;  // weight = 2^(-beta*log2(dt')/ln5)
        #pragma unroll
        for (int r = 0; r < 4; ++r) {
            const int li = (ty << 2) + r;
            #pragma unroll
            for (int q = 0; q < 4; ++q) {
                const int lj = tx + (q << 4);
                float beta = fminf(fmaxf(accB[r][q] + 1.0f, 0.0f), 10.0f);
                float d    = fabsf(tsS[r] - tsT[q]);
                float L    = __log2f(d + 1e-10f);
                float w    = fast_exp2(beta * (NEG_INV_LN5 * L));
                float cr   = accA[r][q] * w;
                if (offdiag || (li < lj)) colsum[q] += cr;   // strict s < t
            }
        }
    }

    // cross-thread column reduction (16 thread-rows per column)
    __syncthreads();
    #pragma unroll
    for (int q = 0; q < 4; ++q) sRed[ty][tx + (q << 4)] = colsum[q];
    __syncthreads();

    if (tid < TT) {
        float s = 0.f;
        #pragma unroll
        for (int r = 0; r < 16; ++r) s += sRed[r][tid];
        float h = g_bias[tgt_base + tid] + s;
        out[tgt_base + tid] = 1.0f / (1.0f + __expf(-h));
    }
}

extern "C" void kernel_launch(void* const* d_in, const int* in_sizes, int n_in,
                              void* d_out, int out_size)
{
    const int*   skills   = (const int*)d_in[0];
    const int*   problems = (const int*)d_in[1];
    const int*   times    = (const int*)d_in[2];
    const int*   labels   = (const int*)d_in[3];
    const float* aI = (const float*)d_in[4];
    const float* aS = (const float*)d_in[5];
    const float* bI = (const float*)d_in[6];
    const float* bS = (const float*)d_in[7];
    const float* pb = (const float*)d_in[8];
    const float* sb = (const float*)d_in[9];
    float* out = (float*)d_out;

    int total = NPOS * (EMB/4);
    gather_kernel<<<(total + 255) / 256, 256>>>(skills, problems, times, labels,
                                                aI, aS, bI, bS, pb, sb);
    dim3 grid(NT, BB);
    hawkes_main<<<grid, 256>>>(out);
}

// round 3
// speedup vs baseline: 10.6811x; 10.6811x over previous
#include <cuda_runtime.h>
#include <cuda_bf16.h>
#include <cstdint>

#define BB 32
#define S_LEN 2048
#define EMB 256
#define NPOS (BB*S_LEN)
#define NSK 1000
#define NT128 16

// ---------- gathered operands (bf16, [pos][256]) ----------
__device__ __nv_bfloat16 g_srcA[NPOS*EMB];
__device__ __nv_bfloat16 g_srcB[NPOS*EMB];
__device__ __nv_bfloat16 g_tgtA[NPOS*EMB];
__device__ __nv_bfloat16 g_tgtB[NPOS*EMB];
__device__ float g_ts[NPOS];
__device__ float g_bias[NPOS];

// ---------- helpers ----------
__device__ __forceinline__ uint32_t smem_u32(const void* p){
    uint32_t a; asm("{ .reg .u64 t; cvta.to.shared.u64 t, %1; cvt.u32.u64 %0, t; }" : "=r"(a) : "l"(p));
    return a;
}
#define CP16(dst, src)  asm volatile("cp.async.cg.shared.global [%0], [%1], 16;" :: "r"(dst), "l"(src) : "memory")
#define CPCOMMIT()      asm volatile("cp.async.commit_group;" ::: "memory")
#define CPWAIT(n)       asm volatile("cp.async.wait_group %0;" :: "n"(n) : "memory")

#define LDSM4(r0,r1,r2,r3,addr) \
    asm volatile("ldmatrix.sync.aligned.m8n8.x4.shared.b16 {%0,%1,%2,%3}, [%4];" \
        : "=r"(r0),"=r"(r1),"=r"(r2),"=r"(r3) : "r"(addr))

#define MMA16816(d, a, b0, b1) \
    asm volatile("mma.sync.aligned.m16n8k16.row.col.f32.bf16.bf16.f32 " \
        "{%0,%1,%2,%3}, {%4,%5,%6,%7}, {%8,%9}, {%0,%1,%2,%3};" \
        : "+f"((d)[0]),"+f"((d)[1]),"+f"((d)[2]),"+f"((d)[3]) \
        : "r"((a)[0]),"r"((a)[1]),"r"((a)[2]),"r"((a)[3]), "r"(b0),"r"(b1))

__device__ __forceinline__ float flg2(float x){ float r; asm("lg2.approx.f32 %0, %1;" : "=f"(r) : "f"(x)); return r; }
__device__ __forceinline__ float fex2(float x){ float r; asm("ex2.approx.f32 %0, %1;" : "=f"(r) : "f"(x)); return r; }

// ---------- SMEM layout (dynamic) ----------
// tgtA: 4 k-chunks x [128 rows x 128B] (swizzled)   65536
// tgtB: +65536
// src:  2 stages x (A 16384 + B 16384)              65536  @131072
// sPart: float[4][128]                              2048   @196608
#define OFF_TGTA   0
#define OFF_TGTB   65536
#define OFF_SRC    131072
#define OFF_PART   196608
#define SMEM_BYTES 198656

// ---------- gather ----------
__global__ void gather_kernel(const int* __restrict__ skills, const int* __restrict__ problems,
                              const int* __restrict__ times,  const int* __restrict__ labels,
                              const float* __restrict__ aI, const float* __restrict__ aS,
                              const float* __restrict__ bI, const float* __restrict__ bS,
                              const float* __restrict__ pb, const float* __restrict__ sb)
{
    int idx = blockIdx.x * blockDim.x + threadIdx.x;
    if (idx >= NPOS * (EMB/4)) return;
    int pos = idx >> 6;
    int e   = (idx & 63) << 2;
    int sk  = skills[pos];
    int inter = sk + labels[pos] * NSK;
    float4 vA = *(const float4*)(aI + (size_t)inter*EMB + e);
    float4 vB = *(const float4*)(bI + (size_t)inter*EMB + e);
    float4 tA = *(const float4*)(aS + (size_t)sk*EMB + e);
    float4 tB = *(const float4*)(bS + (size_t)sk*EMB + e);
    size_t o = (size_t)pos*EMB + e;
    *(__nv_bfloat162*)(g_srcA + o)     = __floats2bfloat162_rn(vA.x, vA.y);
    *(__nv_bfloat162*)(g_srcA + o + 2) = __floats2bfloat162_rn(vA.z, vA.w);
    *(__nv_bfloat162*)(g_srcB + o)     = __floats2bfloat162_rn(vB.x, vB.y);
    *(__nv_bfloat162*)(g_srcB + o + 2) = __floats2bfloat162_rn(vB.z, vB.w);
    *(__nv_bfloat162*)(g_tgtA + o)     = __floats2bfloat162_rn(tA.x, tA.y);
    *(__nv_bfloat162*)(g_tgtA + o + 2) = __floats2bfloat162_rn(tA.z, tA.w);
    *(__nv_bfloat162*)(g_tgtB + o)     = __floats2bfloat162_rn(tB.x, tB.y);
    *(__nv_bfloat162*)(g_tgtB + o + 2) = __floats2bfloat162_rn(tB.z, tB.w);
    if ((idx & 63) == 0) {
        g_ts[pos]   = (float)times[pos] / 1000.0f;
        g_bias[pos] = pb[problems[pos]] + sb[sk];
    }
}

// issue one 128x64 bf16 chunk (both src matrices) into a stage, swizzled
__device__ __forceinline__ void issue_src_chunk(uint32_t stage, int src_base, int kc, int tid)
{
    #pragma unroll
    for (int rep = 0; rep < 4; ++rep) {
        int j   = tid + rep*512;           // 0..2047
        int mat = j >> 10;                 // 0: A, 1: B
        int rem = j & 1023;
        int r   = rem >> 3, u = rem & 7;
        uint32_t dst = stage + mat*16384 + r*128 + ((u ^ (r & 7)) << 4);
        const __nv_bfloat16* g = mat ? g_srcB : g_srcA;
        CP16(dst, g + (size_t)(src_base + r)*EMB + kc*64 + u*8);
    }
}

// ---------- main HMMA kernel ----------
__global__ void __launch_bounds__(512, 1) hawkes_mma(float* __restrict__ out)
{
    extern __shared__ char smem[];
    const uint32_t sb = smem_u32(smem);
    const int tid  = threadIdx.x;
    const int wid  = tid >> 5;
    const int lane = tid & 31;
    const int wm   = wid >> 2;       // source-row group (32 rows)
    const int wn   = wid & 3;        // target-col group (32 cols)

    const int bidx = blockIdx.x;
    const int jt = (NT128 - 1) - (bidx >> 5);   // big tiles first
    const int b  = bidx & 31;
    const int tgt_base = b * S_LEN + jt * 128;

    float* sPart = (float*)(smem + OFF_PART);

    // ---- prologue: target tiles (resident) + src chunks 0,1 ----
    {
        #pragma unroll
        for (int rep = 0; rep < 16; ++rep) {
            int j   = tid + rep*512;           // 0..8191
            int mat = j >> 12;                 // 0: tgtA, 1: tgtB
            int rem = j & 4095;
            int cc  = rem >> 10;               // k-chunk
            int r2  = rem & 1023;
            int r   = r2 >> 3, u = r2 & 7;
            uint32_t dst = sb + (mat ? OFF_TGTB : OFF_TGTA) + cc*16384 + r*128 + ((u ^ (r & 7)) << 4);
            const __nv_bfloat16* g = mat ? g_tgtB : g_tgtA;
            CP16(dst, g + (size_t)(tgt_base + r)*EMB + cc*64 + u*8);
        }
        issue_src_chunk(sb + OFF_SRC, b * S_LEN, 0, tid);
        CPCOMMIT();                                     // group: tgt + chunk0
        issue_src_chunk(sb + OFF_SRC + 32768, b * S_LEN, 1, tid);
        CPCOMMIT();                                     // group: chunk1
        CPWAIT(1);
        __syncthreads();
    }

    // ---- per-lane constant addressing ----
    const int rA0 = wm*32 + (lane & 15);       // msub0 source row (local)
    const int rA1 = rA0 + 16;                  // msub1
    const uint32_t offA0 = rA0*128, offA1 = rA1*128;
    const uint32_t xA0 = rA0 & 7,  xA1 = rA1 & 7;
    const uint32_t uAbase = (uint32_t)(lane >> 4);           // +0/+1 16B unit

    const int rB0 = wn*32 + (lane & 7) + ((lane >> 4) << 3); // npair0 target row
    const int rB1 = rB0 + 16;                                // npair1
    const uint32_t offB0 = rB0*128, offB1 = rB1*128;
    const uint32_t xB0 = rB0 & 7,  xB1 = rB1 & 7;
    const uint32_t uBbase = (uint32_t)((lane >> 3) & 1);

    // target-time per owned column (4 nsub x 2 cols)
    float tsT[4][2];
    #pragma unroll
    for (int ns = 0; ns < 4; ++ns) {
        int c0 = wn*32 + ns*8 + 2*(lane & 3);
        tsT[ns][0] = g_ts[tgt_base + c0];
        tsT[ns][1] = g_ts[tgt_base + c0 + 1];
    }

    float colsum[4][2];
    #pragma unroll
    for (int ns = 0; ns < 4; ++ns) { colsum[ns][0] = 0.f; colsum[ns][1] = 0.f; }

    const int G = (jt + 1) * 4;
    const float NEG_INV_LN5 = -0.6213349345596119f;

    for (int it = 0; it <= jt; ++it) {
        float accA[2][4][4], accB[2][4][4];
        #pragma unroll
        for (int m = 0; m < 2; ++m)
            #pragma unroll
            for (int n = 0; n < 4; ++n)
                #pragma unroll
                for (int e = 0; e < 4; ++e) { accA[m][n][e] = 0.f; accB[m][n][e] = 0.f; }

        #pragma unroll 1
        for (int kc = 0; kc < 4; ++kc) {
            const int g = it*4 + kc;
            const uint32_t stA = sb + OFF_SRC + (g & 1)*32768;
            const uint32_t stB = stA + 16384;
            const uint32_t tgA = sb + OFF_TGTA + kc*16384;
            const uint32_t tgB = sb + OFF_TGTB + kc*16384;

            #pragma unroll
            for (int kk = 0; kk < 4; ++kk) {
                const uint32_t uA = kk*2 + uAbase;
                const uint32_t uB = kk*2 + uBbase;
                uint32_t aA0[4], aA1[4], aB0[4], aB1[4];
                uint32_t bA0[4], bA1[4], bB0[4], bB1[4];
                LDSM4(aA0[0],aA0[1],aA0[2],aA0[3], stA + offA0 + (((uA ^ xA0)) << 4));
                LDSM4(aA1[0],aA1[1],aA1[2],aA1[3], stA + offA1 + (((uA ^ xA1)) << 4));
                LDSM4(aB0[0],aB0[1],aB0[2],aB0[3], stB + offA0 + (((uA ^ xA0)) << 4));
                LDSM4(aB1[0],aB1[1],aB1[2],aB1[3], stB + offA1 + (((uA ^ xA1)) << 4));
                LDSM4(bA0[0],bA0[1],bA0[2],bA0[3], tgA + offB0 + (((uB ^ xB0)) << 4));
                LDSM4(bA1[0],bA1[1],bA1[2],bA1[3], tgA + offB1 + (((uB ^ xB1)) << 4));
                LDSM4(bB0[0],bB0[1],bB0[2],bB0[3], tgB + offB0 + (((uB ^ xB0)) << 4));
                LDSM4(bB1[0],bB1[1],bB1[2],bB1[3], tgB + offB1 + (((uB ^ xB1)) << 4));

                MMA16816(accA[0][0], aA0, bA0[0], bA0[1]);
                MMA16816(accA[0][1], aA0, bA0[2], bA0[3]);
                MMA16816(accA[0][2], aA0, bA1[0], bA1[1]);
                MMA16816(accA[0][3], aA0, bA1[2], bA1[3]);
                MMA16816(accA[1][0], aA1, bA0[0], bA0[1]);
                MMA16816(accA[1][1], aA1, bA0[2], bA0[3]);
                MMA16816(accA[1][2], aA1, bA1[0], bA1[1]);
                MMA16816(accA[1][3], aA1, bA1[2], bA1[3]);

                MMA16816(accB[0][0], aB0, bB0[0], bB0[1]);
                MMA16816(accB[0][1], aB0, bB0[2], bB0[3]);
                MMA16816(accB[0][2], aB0, bB1[0], bB1[1]);
                MMA16816(accB[0][3], aB0, bB1[2], bB1[3]);
                MMA16816(accB[1][0], aB1, bB0[0], bB0[1]);
                MMA16816(accB[1][1], aB1, bB0[2], bB0[3]);
                MMA16816(accB[1][2], aB1, bB1[0], bB1[1]);
                MMA16816(accB[1][3], aB1, bB1[2], bB1[3]);
            }

            __syncthreads();                         // everyone done reading stage g&1
            if (g + 2 < G) {
                const int gn = g + 2;
                issue_src_chunk(sb + OFF_SRC + (gn & 1)*32768, b * S_LEN + (gn >> 2)*128, gn & 3, tid);
            }
            CPCOMMIT();
            CPWAIT(1);                               // chunk g+1 resident
            __syncthreads();
        }

        // ---- epilogue for this source tile ----
        const int src_base = b * S_LEN + it * 128;
        const bool diag = (it == jt);
        #pragma unroll
        for (int m = 0; m < 2; ++m) {
            const int rlo = wm*32 + m*16 + (lane >> 2);
            const float tsS_lo = g_ts[src_base + rlo];
            const float tsS_hi = g_ts[src_base + rlo + 8];
            #pragma unroll
            for (int n = 0; n < 4; ++n) {
                const int c0 = wn*32 + n*8 + 2*(lane & 3);
                #pragma unroll
                for (int e = 0; e < 4; ++e) {
                    const float tsS = (e < 2) ? tsS_lo : tsS_hi;
                    const int   r_l = (e < 2) ? rlo : rlo + 8;
                    const int   c_l = c0 + (e & 1);
                    float beta = fminf(fmaxf(accB[m][n][e] + 1.0f, 0.0f), 10.0f);
                    float d    = fabsf(tsS - tsT[n][e & 1]) + 1e-10f;
                    float L    = flg2(d);
                    float w    = fex2(beta * (L * NEG_INV_LN5));
                    float cr   = accA[m][n][e] * w;
                    if (!diag || (r_l < c_l)) colsum[n][e & 1] += cr;
                }
            }
        }
    }

    // ---- cross-lane column reduce ----
    #pragma unroll
    for (int n = 0; n < 4; ++n)
        #pragma unroll
        for (int p = 0; p < 2; ++p) {
            float v = colsum[n][p];
            v += __shfl_xor_sync(0xffffffffu, v, 4);
            v += __shfl_xor_sync(0xffffffffu, v, 8);
            v += __shfl_xor_sync(0xffffffffu, v, 16);
            colsum[n][p] = v;
        }
    __syncthreads();   // sPart aliasing vs earlier use: first use, just order with loads
    if (lane < 4) {
        #pragma unroll
        for (int n = 0; n < 4; ++n) {
            int c = wn*32 + n*8 + 2*lane;
            if (wm == 0) { sPart[0*128 + c] = colsum[n][0]; sPart[0*128 + c + 1] = colsum[n][1]; }
            if (wm == 1) { sPart[1*128 + c] = colsum[n][0]; sPart[1*128 + c + 1] = colsum[n][1]; }
            if (wm == 2) { sPart[2*128 + c] = colsum[n][0]; sPart[2*128 + c + 1] = colsum[n][1]; }
            if (wm == 3) { sPart[3*128 + c] = colsum[n][0]; sPart[3*128 + c + 1] = colsum[n][1]; }
        }
    }
    __syncthreads();

    if (tid < 128) {
        float s = sPart[tid] + sPart[128 + tid] + sPart[256 + tid] + sPart[384 + tid];
        float h = g_bias[tgt_base + tid] + s;
        out[tgt_base + tid] = 1.0f / (1.0f + fex2(-h * 1.4426950408889634f) ) ;
    }
}

extern "C" void kernel_launch(void* const* d_in, const int* in_sizes, int n_in,
                              void* d_out, int out_size)
{
    const int*   skills   = (const int*)d_in[0];
    const int*   problems = (const int*)d_in[1];
    const int*   times    = (const int*)d_in[2];
    const int*   labels   = (const int*)d_in[3];
    const float* aI = (const float*)d_in[4];
    const float* aS = (const float*)d_in[5];
    const float* bI = (const float*)d_in[6];
    const float* bS = (const float*)d_in[7];
    const float* pb = (const float*)d_in[8];
    const float* sb = (const float*)d_in[9];
    float* out = (float*)d_out;

    static bool attr_done = false;
    if (!attr_done) {
        cudaFuncSetAttribute(hawkes_mma, cudaFuncAttributeMaxDynamicSharedMemorySize, SMEM_BYTES);
        attr_done = true;
    }

    int total = NPOS * (EMB/4);
    gather_kernel<<<(total + 255) / 256, 256>>>(skills, problems, times, labels,
                                                aI, aS, bI, bS, pb, sb);
    hawkes_mma<<<NT128 * BB, 512, SMEM_BYTES>>>(out);
}